// round 1
// baseline (speedup 1.0000x reference)
#include <cuda_runtime.h>
#include <cuda_bf16.h>
#include <cstdint>

// out[b,u] = ||x_b||^2 - 2 * (x@w)[b,u] + ||w_u||^2
// x: [65536, 256] f32 row-major, w: [256, 1024] f32 row-major, out: [65536, 1024] f32
//
// Strategy: bf16 mma.sync GEMM (fp32 accum), CTA tile 128x128, full K=256 in SMEM.
// x_sq computed during A staging (warp reduce), w_sq by a tiny prep kernel.

#define B_DIM 65536
#define F_DIM 256
#define U_DIM 1024

#define LDA 264   // 256 + 8 bf16 pad (528B row stride -> conflict-free ldmatrix)
#define LDB 136   // 128 + 8 bf16 pad (272B row stride)

#define SMEM_A_BYTES (128 * LDA * 2)            // 67584
#define SMEM_B_BYTES (256 * LDB * 2)            // 69632
#define SMEM_XSQ_OFF (SMEM_A_BYTES + SMEM_B_BYTES)
#define SMEM_TOTAL   (SMEM_XSQ_OFF + 128 * 4 + 128)

__device__ float g_wsq[U_DIM];

__global__ void wsq_kernel(const float* __restrict__ w) {
    int u = blockIdx.x * blockDim.x + threadIdx.x;
    if (u >= U_DIM) return;
    float s = 0.f;
#pragma unroll 8
    for (int f = 0; f < F_DIM; f++) {
        float v = w[f * U_DIM + u];
        s = fmaf(v, v, s);
    }
    g_wsq[u] = s;
}

__device__ __forceinline__ void ldm_x4(uint32_t& r0, uint32_t& r1, uint32_t& r2, uint32_t& r3,
                                       uint32_t addr) {
    asm volatile("ldmatrix.sync.aligned.m8n8.x4.shared.b16 {%0,%1,%2,%3}, [%4];"
                 : "=r"(r0), "=r"(r1), "=r"(r2), "=r"(r3) : "r"(addr));
}

__device__ __forceinline__ void ldm_x4_trans(uint32_t& r0, uint32_t& r1, uint32_t& r2, uint32_t& r3,
                                             uint32_t addr) {
    asm volatile("ldmatrix.sync.aligned.m8n8.x4.trans.shared.b16 {%0,%1,%2,%3}, [%4];"
                 : "=r"(r0), "=r"(r1), "=r"(r2), "=r"(r3) : "r"(addr));
}

__device__ __forceinline__ void mma_16816(float* c, const uint32_t* a, const uint32_t* b) {
    asm volatile("mma.sync.aligned.m16n8k16.row.col.f32.bf16.bf16.f32 "
                 "{%0,%1,%2,%3}, {%4,%5,%6,%7}, {%8,%9}, {%0,%1,%2,%3};"
                 : "+f"(c[0]), "+f"(c[1]), "+f"(c[2]), "+f"(c[3])
                 : "r"(a[0]), "r"(a[1]), "r"(a[2]), "r"(a[3]), "r"(b[0]), "r"(b[1]));
}

__global__ __launch_bounds__(256, 1)
void rbf_gemm_kernel(const float* __restrict__ x, const float* __restrict__ w,
                     float* __restrict__ out) {
    extern __shared__ char smem[];
    __nv_bfloat16* As = reinterpret_cast<__nv_bfloat16*>(smem);
    __nv_bfloat16* Bs = reinterpret_cast<__nv_bfloat16*>(smem + SMEM_A_BYTES);
    float* xsq_s = reinterpret_cast<float*>(smem + SMEM_XSQ_OFF);

    const int tid = threadIdx.x;
    const int lane = tid & 31;
    const int wi = tid >> 5;          // 0..7
    const int warp_m = wi & 3;        // 4 warps along M (32 rows each)
    const int warp_n = wi >> 2;       // 2 warps along N (64 cols each)
    const int m0 = blockIdx.y * 128;
    const int n0 = blockIdx.x * 128;

    if (tid < 128) xsq_s[tid] = 0.f;
    __syncthreads();

    // ---- Stage A: x[m0:m0+128, 0:256] f32 -> bf16 SMEM, + per-row squared sums ----
    {
        const float4* xg = reinterpret_cast<const float4*>(x + (size_t)m0 * F_DIM);
#pragma unroll 4
        for (int it = 0; it < 32; it++) {
            int idx = it * 256 + tid;
            int row = idx >> 6;       // 64 float4 per row
            int c4 = idx & 63;
            float4 v = xg[row * 64 + c4];
            float ps = v.x * v.x + v.y * v.y + v.z * v.z + v.w * v.w;
            // all 32 lanes of this warp are in the same row
#pragma unroll
            for (int o = 16; o > 0; o >>= 1) ps += __shfl_down_sync(0xffffffffu, ps, o);
            if (lane == 0) atomicAdd(&xsq_s[row], ps);
            __nv_bfloat162 p0 = __floats2bfloat162_rn(v.x, v.y);
            __nv_bfloat162 p1 = __floats2bfloat162_rn(v.z, v.w);
            uint2 pk;
            pk.x = *reinterpret_cast<uint32_t*>(&p0);
            pk.y = *reinterpret_cast<uint32_t*>(&p1);
            *reinterpret_cast<uint2*>(As + row * LDA + c4 * 4) = pk;
        }
    }
    // ---- Stage B: w[0:256, n0:n0+128] f32 -> bf16 SMEM ----
    {
        const float* wg = w + n0;
#pragma unroll 4
        for (int it = 0; it < 32; it++) {
            int idx = it * 256 + tid;
            int row = idx >> 5;       // 32 float4 per row
            int c4 = idx & 31;
            float4 v = *reinterpret_cast<const float4*>(wg + row * U_DIM + c4 * 4);
            __nv_bfloat162 p0 = __floats2bfloat162_rn(v.x, v.y);
            __nv_bfloat162 p1 = __floats2bfloat162_rn(v.z, v.w);
            uint2 pk;
            pk.x = *reinterpret_cast<uint32_t*>(&p0);
            pk.y = *reinterpret_cast<uint32_t*>(&p1);
            *reinterpret_cast<uint2*>(Bs + row * LDB + c4 * 4) = pk;
        }
    }
    __syncthreads();

    // ---- Mainloop: K = 256, k-step 16, warp tile 32(M) x 64(N) ----
    float acc[2][8][4];
#pragma unroll
    for (int mt = 0; mt < 2; mt++)
#pragma unroll
        for (int nt = 0; nt < 8; nt++)
#pragma unroll
            for (int i = 0; i < 4; i++) acc[mt][nt][i] = 0.f;

    const uint32_t As_u = (uint32_t)__cvta_generic_to_shared(As);
    const uint32_t Bs_u = (uint32_t)__cvta_generic_to_shared(Bs);
    const int lr = lane & 15;
    const int lc = lane >> 4;  // 0/1

#pragma unroll
    for (int k0 = 0; k0 < 256; k0 += 16) {
        uint32_t a_frag[2][4];
#pragma unroll
        for (int mt = 0; mt < 2; mt++) {
            int row = warp_m * 32 + mt * 16 + lr;
            uint32_t addr = As_u + (uint32_t)(row * LDA + k0 + lc * 8) * 2u;
            ldm_x4(a_frag[mt][0], a_frag[mt][1], a_frag[mt][2], a_frag[mt][3], addr);
        }
        uint32_t b_frag[8][2];
#pragma unroll
        for (int np = 0; np < 4; np++) {
            int col = warp_n * 64 + np * 16 + lc * 8;
            uint32_t addr = Bs_u + (uint32_t)((k0 + lr) * LDB + col) * 2u;
            uint32_t r0, r1, r2, r3;
            ldm_x4_trans(r0, r1, r2, r3, addr);
            b_frag[np * 2][0] = r0; b_frag[np * 2][1] = r1;
            b_frag[np * 2 + 1][0] = r2; b_frag[np * 2 + 1][1] = r3;
        }
#pragma unroll
        for (int mt = 0; mt < 2; mt++)
#pragma unroll
            for (int nt = 0; nt < 8; nt++)
                mma_16816(acc[mt][nt], a_frag[mt], b_frag[nt]);
    }

    // ---- Epilogue: out = xsq[row] + wsq[col] - 2 * cross ----
    const int g = lane >> 2;
    const int cq = (lane & 3) * 2;
#pragma unroll
    for (int mt = 0; mt < 2; mt++) {
        int rloc = warp_m * 32 + mt * 16 + g;
        float xlo = xsq_s[rloc];
        float xhi = xsq_s[rloc + 8];
        size_t row_lo = (size_t)(m0 + rloc) * U_DIM;
        size_t row_hi = row_lo + (size_t)8 * U_DIM;
#pragma unroll
        for (int nt = 0; nt < 8; nt++) {
            int col = n0 + warp_n * 64 + nt * 8 + cq;
            float w0 = g_wsq[col];
            float w1 = g_wsq[col + 1];
            float2 vlo, vhi;
            vlo.x = fmaf(-2.f, acc[mt][nt][0], xlo + w0);
            vlo.y = fmaf(-2.f, acc[mt][nt][1], xlo + w1);
            vhi.x = fmaf(-2.f, acc[mt][nt][2], xhi + w0);
            vhi.y = fmaf(-2.f, acc[mt][nt][3], xhi + w1);
            *reinterpret_cast<float2*>(out + row_lo + col) = vlo;
            *reinterpret_cast<float2*>(out + row_hi + col) = vhi;
        }
    }
}

extern "C" void kernel_launch(void* const* d_in, const int* in_sizes, int n_in,
                              void* d_out, int out_size) {
    const float* x = (const float*)d_in[0];
    const float* w = (const float*)d_in[1];
    float* out = (float*)d_out;

    cudaFuncSetAttribute(rbf_gemm_kernel, cudaFuncAttributeMaxDynamicSharedMemorySize,
                         SMEM_TOTAL);

    wsq_kernel<<<U_DIM / 256, 256>>>(w);

    dim3 grid(U_DIM / 128, B_DIM / 128);   // N fastest -> x-tile reuse within a wave
    rbf_gemm_kernel<<<grid, 256, SMEM_TOTAL>>>(x, w, out);
}

// round 3
// speedup vs baseline: 2.2293x; 2.2293x over previous
#include <cuda_runtime.h>
#include <cuda_bf16.h>
#include <cstdint>

// out[b,u] = ||x_b||^2 - 2 * (x@w)[b,u] + ||w_u||^2
// x: [65536,256] f32, w: [256,1024] f32, out: [65536,1024] f32
//
// sm_103 (no 'a' features available to ptxas here) -> mma.sync.m16n8k16.bf16 path.
// Persistent CTAs: fixed u-tile (w tile resident in smem), stream x k-chunks with
// a 4-stage cp.async pipeline. XOR-swizzled smem, conflict-free ldmatrix.

#define B_DIM 65536
#define F_DIM 256
#define U_DIM 1024
#define TILE  128
#define NB_TILES (B_DIM / TILE)   // 512
#define NU_TILES (U_DIM / TILE)   // 8
#define NSLICE   18               // 8 * 18 = 144 CTAs (one wave on 148 SMs)
#define NS       4                // cp.async pipeline stages (A chunks)

__device__ __nv_bfloat16 g_xbf[(size_t)B_DIM * F_DIM];  // 32 MB
__device__ __nv_bfloat16 g_wbf[(size_t)F_DIM * U_DIM];  // 512 KB, same [f][u] layout
__device__ float g_xsq[B_DIM];
__device__ float g_wsq[U_DIM];

// smem: B tile 64KB | A ring 4x16KB | wsq 512B
#define SM_B    0
#define SM_A    65536
#define SM_WSQ  (65536 + NS * 16384)
#define SM_TOT  (SM_WSQ + 512 + 16)

// ---------------------------------------------------------------- helpers
__device__ __forceinline__ uint32_t smem_u32(const void* p) {
    uint32_t a;
    asm("{ .reg .u64 t; cvta.to.shared.u64 t, %1; cvt.u32.u64 %0, t; }" : "=r"(a) : "l"(p));
    return a;
}
__device__ __forceinline__ void cp16(uint32_t dst, const void* src) {
    asm volatile("cp.async.cg.shared.global [%0], [%1], 16;"
                 :: "r"(dst), "l"(__cvta_generic_to_global(src)) : "memory");
}
#define CP_COMMIT() asm volatile("cp.async.commit_group;" ::: "memory")
#define CP_WAIT(N)  asm volatile("cp.async.wait_group %0;" :: "n"(N) : "memory")

__device__ __forceinline__ void ldm_x4(uint32_t& r0, uint32_t& r1, uint32_t& r2, uint32_t& r3,
                                       uint32_t addr) {
    asm volatile("ldmatrix.sync.aligned.m8n8.x4.shared.b16 {%0,%1,%2,%3}, [%4];"
                 : "=r"(r0), "=r"(r1), "=r"(r2), "=r"(r3) : "r"(addr));
}
__device__ __forceinline__ void ldm_x4_t(uint32_t& r0, uint32_t& r1, uint32_t& r2, uint32_t& r3,
                                         uint32_t addr) {
    asm volatile("ldmatrix.sync.aligned.m8n8.x4.trans.shared.b16 {%0,%1,%2,%3}, [%4];"
                 : "=r"(r0), "=r"(r1), "=r"(r2), "=r"(r3) : "r"(addr));
}
__device__ __forceinline__ void mma_16816(float* c, const uint32_t* a, const uint32_t* b) {
    asm volatile("mma.sync.aligned.m16n8k16.row.col.f32.bf16.bf16.f32 "
                 "{%0,%1,%2,%3}, {%4,%5,%6,%7}, {%8,%9}, {%0,%1,%2,%3};"
                 : "+f"(c[0]), "+f"(c[1]), "+f"(c[2]), "+f"(c[3])
                 : "r"(a[0]), "r"(a[1]), "r"(a[2]), "r"(a[3]), "r"(b[0]), "r"(b[1]));
}

// ---------------------------------------------------------------- prep kernels
__global__ void xprep_kernel(const float* __restrict__ x) {
    int row = blockIdx.x * 8 + (threadIdx.x >> 5);
    int lane = threadIdx.x & 31;
    const float4* src = reinterpret_cast<const float4*>(x + (size_t)row * F_DIM);
    float4 a = src[lane], b = src[lane + 32];
    float s = a.x * a.x + a.y * a.y + a.z * a.z + a.w * a.w
            + b.x * b.x + b.y * b.y + b.z * b.z + b.w * b.w;
#pragma unroll
    for (int o = 16; o > 0; o >>= 1) s += __shfl_down_sync(0xffffffffu, s, o);
    if (lane == 0) g_xsq[row] = s;
    uint2* dst = reinterpret_cast<uint2*>(g_xbf + (size_t)row * F_DIM);
    __nv_bfloat162 p0 = __floats2bfloat162_rn(a.x, a.y), p1 = __floats2bfloat162_rn(a.z, a.w);
    __nv_bfloat162 q0 = __floats2bfloat162_rn(b.x, b.y), q1 = __floats2bfloat162_rn(b.z, b.w);
    uint2 u0, u1;
    u0.x = *reinterpret_cast<uint32_t*>(&p0); u0.y = *reinterpret_cast<uint32_t*>(&p1);
    u1.x = *reinterpret_cast<uint32_t*>(&q0); u1.y = *reinterpret_cast<uint32_t*>(&q1);
    dst[lane] = u0; dst[lane + 32] = u1;
}

__global__ void wprep_kernel(const float* __restrict__ w) {
    int i = blockIdx.x * blockDim.x + threadIdx.x;  // 1 float4 per thread
    float4 v = reinterpret_cast<const float4*>(w)[i];
    __nv_bfloat162 p0 = __floats2bfloat162_rn(v.x, v.y), p1 = __floats2bfloat162_rn(v.z, v.w);
    uint2 u;
    u.x = *reinterpret_cast<uint32_t*>(&p0); u.y = *reinterpret_cast<uint32_t*>(&p1);
    reinterpret_cast<uint2*>(g_wbf)[i] = u;
}

__global__ void wsq_kernel(const float* __restrict__ w) {
    int u = blockIdx.x * blockDim.x + threadIdx.x;
    float s = 0.f;
#pragma unroll 8
    for (int f = 0; f < F_DIM; f++) {
        float v = w[(size_t)f * U_DIM + u];
        s = fmaf(v, v, s);
    }
    g_wsq[u] = s;
}

// ---------------------------------------------------------------- GEMM
__global__ __launch_bounds__(256, 1)
void rbf_gemm_kernel(float* __restrict__ out) {
    extern __shared__ char smem[];
    const uint32_t sb = smem_u32(smem);
    const int tid = threadIdx.x, lane = tid & 31, wi = tid >> 5;
    const int warp_m = wi & 3, warp_n = wi >> 2;

    const int u_tile = blockIdx.x & 7;          // u fastest -> 8 CTAs share each x-slice via L2
    const int slice = blockIdx.x >> 3;
    const int u0 = u_tile * TILE;
    const int b_begin = (slice * NB_TILES) / NSLICE;
    const int b_end = ((slice + 1) * NB_TILES) / NSLICE;
    const int C = (b_end - b_begin) * 4;        // k-chunks total

    // ---- B (w tile, full K=256) : 4096 16B chunks, swizzled ----
    for (int i = tid; i < 4096; i += 256) {
        int k = i >> 4, c = i & 15;
        uint32_t dst = sb + SM_B + (uint32_t)(k * 256 + ((c ^ (k & 7)) << 4));
        cp16(dst, (const char*)(g_wbf + (size_t)k * U_DIM + u0) + c * 16);
    }
    // wsq into smem
    if (tid < 32) {
        float4 v = reinterpret_cast<const float4*>(g_wsq + u0)[tid];
        reinterpret_cast<float4*>(smem + SM_WSQ)[tid] = v;
    }
    CP_COMMIT();

    // ---- prologue: A chunks 0..NS-1 ----
    for (int c = 0; c < NS && c < C; c++) {
        size_t base = ((size_t)(b_begin + (c >> 2)) * TILE) * F_DIM + (size_t)(c & 3) * 64;
        uint32_t abuf = sb + SM_A + (uint32_t)((c % NS) * 16384);
        for (int i = tid; i < 1024; i += 256) {
            int r = i >> 3, cc = i & 7;
            cp16(abuf + (uint32_t)(r * 128 + ((cc ^ (r & 7)) << 4)),
                 g_xbf + base + (size_t)r * F_DIM + cc * 8);
        }
        CP_COMMIT();
    }

    float acc[2][8][4];
    const int lr = lane & 15, lc = lane >> 4;
    const int g = lane >> 2, cq = (lane & 3) * 2;
    const float* ws = reinterpret_cast<const float*>(smem + SM_WSQ);

    for (int c = 0; c < C; c++) {
        const int kc = c & 3;
        CP_WAIT(NS - 1);
        __syncthreads();

        if (kc == 0) {
#pragma unroll
            for (int mt = 0; mt < 2; mt++)
#pragma unroll
                for (int nt = 0; nt < 8; nt++)
#pragma unroll
                    for (int i = 0; i < 4; i++) acc[mt][nt][i] = 0.f;
        }

        // ---- compute chunk: 64 k, 4 k-steps ----
        const uint32_t abuf = sb + SM_A + (uint32_t)((c % NS) * 16384);
#pragma unroll
        for (int kk = 0; kk < 64; kk += 16) {
            uint32_t a_frag[2][4];
#pragma unroll
            for (int mt = 0; mt < 2; mt++) {
                int r = warp_m * 32 + mt * 16 + lr;
                int cch = (kk >> 3) + lc;
                uint32_t addr = abuf + (uint32_t)(r * 128 + ((cch ^ (r & 7)) << 4));
                ldm_x4(a_frag[mt][0], a_frag[mt][1], a_frag[mt][2], a_frag[mt][3], addr);
            }
            uint32_t b_frag[8][2];
#pragma unroll
            for (int np = 0; np < 4; np++) {
                int krow = kc * 64 + kk + lr;
                int cch = warp_n * 8 + np * 2 + lc;
                uint32_t addr = sb + SM_B + (uint32_t)(krow * 256 + ((cch ^ (krow & 7)) << 4));
                uint32_t r0, r1, r2, r3;
                ldm_x4_t(r0, r1, r2, r3, addr);
                b_frag[np * 2][0] = r0;     b_frag[np * 2][1] = r1;
                b_frag[np * 2 + 1][0] = r2; b_frag[np * 2 + 1][1] = r3;
            }
#pragma unroll
            for (int mt = 0; mt < 2; mt++)
#pragma unroll
                for (int nt = 0; nt < 8; nt++)
                    mma_16816(acc[mt][nt], a_frag[mt], b_frag[nt]);
        }
        __syncthreads();

        // ---- refill this buffer with chunk c+NS ----
        if (c + NS < C) {
            int cn = c + NS;
            size_t base = ((size_t)(b_begin + (cn >> 2)) * TILE) * F_DIM + (size_t)(cn & 3) * 64;
            for (int i = tid; i < 1024; i += 256) {
                int r = i >> 3, cc = i & 7;
                cp16(abuf + (uint32_t)(r * 128 + ((cc ^ (r & 7)) << 4)),
                     g_xbf + base + (size_t)r * F_DIM + cc * 8);
            }
        }
        CP_COMMIT();

        // ---- epilogue (overlaps the in-flight cp.async) ----
        if (kc == 3) {
            int bt = b_begin + (c >> 2);
#pragma unroll
            for (int mt = 0; mt < 2; mt++) {
                int rloc = warp_m * 32 + mt * 16 + g;
                float xlo = __ldg(&g_xsq[bt * TILE + rloc]);
                float xhi = __ldg(&g_xsq[bt * TILE + rloc + 8]);
                size_t row_lo = (size_t)(bt * TILE + rloc) * U_DIM;
                size_t row_hi = row_lo + (size_t)8 * U_DIM;
#pragma unroll
                for (int nt = 0; nt < 8; nt++) {
                    int cloc = warp_n * 64 + nt * 8 + cq;
                    float w0 = ws[cloc], w1 = ws[cloc + 1];
                    float2 vlo, vhi;
                    vlo.x = fmaf(-2.f, acc[mt][nt][0], xlo + w0);
                    vlo.y = fmaf(-2.f, acc[mt][nt][1], xlo + w1);
                    vhi.x = fmaf(-2.f, acc[mt][nt][2], xhi + w0);
                    vhi.y = fmaf(-2.f, acc[mt][nt][3], xhi + w1);
                    __stcs(reinterpret_cast<float2*>(out + row_lo + u0 + cloc), vlo);
                    __stcs(reinterpret_cast<float2*>(out + row_hi + u0 + cloc), vhi);
                }
            }
        }
    }
}

extern "C" void kernel_launch(void* const* d_in, const int* in_sizes, int n_in,
                              void* d_out, int out_size) {
    const float* x = (const float*)d_in[0];
    const float* w = (const float*)d_in[1];
    float* out = (float*)d_out;

    cudaFuncSetAttribute(rbf_gemm_kernel, cudaFuncAttributeMaxDynamicSharedMemorySize, SM_TOT);

    xprep_kernel<<<B_DIM / 8, 256>>>(x);
    wprep_kernel<<<(F_DIM * U_DIM / 4) / 256, 256>>>(w);
    wsq_kernel<<<U_DIM / 256, 256>>>(w);
    rbf_gemm_kernel<<<NU_TILES * NSLICE, 256, SM_TOT>>>(out);
}

// round 4
// speedup vs baseline: 2.6968x; 1.2097x over previous
#include <cuda_runtime.h>
#include <cuda_bf16.h>
#include <cstdint>

// out[b,u] = ||x_b||^2 - 2 * (x@w)[b,u] + ||w_u||^2
// x: [65536,256] f32, w: [256,1024] f32, out: [65536,1024] f32
//
// mma.sync.m16n8k16.bf16 path (plain sm_103 target). Persistent CTAs, 2 CTAs/SM:
// fixed u-tile (w tile resident in smem), stream x k-chunks through a 3-stage
// cp.async ring. XOR-swizzled smem, conflict-free ldmatrix.

#define B_DIM 65536
#define F_DIM 256
#define U_DIM 1024
#define TILE  128
#define NB_TILES (B_DIM / TILE)   // 512
#define NU_TILES (U_DIM / TILE)   // 8
#define NSLICE   36               // 8 * 36 = 288 CTAs = 2 waves-in-residence on 144 SMs
#define NS       3                // cp.async ring stages (16KB each)

__device__ __nv_bfloat16 g_xbf[(size_t)B_DIM * F_DIM];  // 32 MB
__device__ __nv_bfloat16 g_wbf[(size_t)F_DIM * U_DIM];  // 512 KB
__device__ float g_xsq[B_DIM];
__device__ float g_wsq[U_DIM];

// smem: B tile 64KB | A ring 3x16KB | wsq 512B   => 115200 B/CTA (2 fit per SM)
#define SM_B    0
#define SM_A    65536
#define SM_WSQ  (65536 + NS * 16384)
#define SM_TOT  (SM_WSQ + 512)

// ---------------------------------------------------------------- helpers
__device__ __forceinline__ uint32_t smem_u32(const void* p) {
    uint32_t a;
    asm("{ .reg .u64 t; cvta.to.shared.u64 t, %1; cvt.u32.u64 %0, t; }" : "=r"(a) : "l"(p));
    return a;
}
__device__ __forceinline__ void cp16(uint32_t dst, const void* src) {
    asm volatile("cp.async.cg.shared.global [%0], [%1], 16;"
                 :: "r"(dst), "l"(__cvta_generic_to_global(src)) : "memory");
}
#define CP_COMMIT() asm volatile("cp.async.commit_group;" ::: "memory")
#define CP_WAIT(N)  asm volatile("cp.async.wait_group %0;" :: "n"(N) : "memory")

__device__ __forceinline__ void ldm_x4(uint32_t& r0, uint32_t& r1, uint32_t& r2, uint32_t& r3,
                                       uint32_t addr) {
    asm volatile("ldmatrix.sync.aligned.m8n8.x4.shared.b16 {%0,%1,%2,%3}, [%4];"
                 : "=r"(r0), "=r"(r1), "=r"(r2), "=r"(r3) : "r"(addr));
}
__device__ __forceinline__ void ldm_x4_t(uint32_t& r0, uint32_t& r1, uint32_t& r2, uint32_t& r3,
                                         uint32_t addr) {
    asm volatile("ldmatrix.sync.aligned.m8n8.x4.trans.shared.b16 {%0,%1,%2,%3}, [%4];"
                 : "=r"(r0), "=r"(r1), "=r"(r2), "=r"(r3) : "r"(addr));
}
__device__ __forceinline__ void mma_16816(float* c, const uint32_t* a, const uint32_t* b) {
    asm volatile("mma.sync.aligned.m16n8k16.row.col.f32.bf16.bf16.f32 "
                 "{%0,%1,%2,%3}, {%4,%5,%6,%7}, {%8,%9}, {%0,%1,%2,%3};"
                 : "+f"(c[0]), "+f"(c[1]), "+f"(c[2]), "+f"(c[3])
                 : "r"(a[0]), "r"(a[1]), "r"(a[2]), "r"(a[3]), "r"(b[0]), "r"(b[1]));
}

// ---------------------------------------------------------------- prep kernels
__global__ void xprep_kernel(const float* __restrict__ x) {
    int row = blockIdx.x * 8 + (threadIdx.x >> 5);
    int lane = threadIdx.x & 31;
    const float4* src = reinterpret_cast<const float4*>(x + (size_t)row * F_DIM);
    float4 a = src[lane], b = src[lane + 32];
    float s = a.x * a.x + a.y * a.y + a.z * a.z + a.w * a.w
            + b.x * b.x + b.y * b.y + b.z * b.z + b.w * b.w;
#pragma unroll
    for (int o = 16; o > 0; o >>= 1) s += __shfl_down_sync(0xffffffffu, s, o);
    if (lane == 0) g_xsq[row] = s;
    uint2* dst = reinterpret_cast<uint2*>(g_xbf + (size_t)row * F_DIM);
    __nv_bfloat162 p0 = __floats2bfloat162_rn(a.x, a.y), p1 = __floats2bfloat162_rn(a.z, a.w);
    __nv_bfloat162 q0 = __floats2bfloat162_rn(b.x, b.y), q1 = __floats2bfloat162_rn(b.z, b.w);
    uint2 u0, u1;
    u0.x = *reinterpret_cast<uint32_t*>(&p0); u0.y = *reinterpret_cast<uint32_t*>(&p1);
    u1.x = *reinterpret_cast<uint32_t*>(&q0); u1.y = *reinterpret_cast<uint32_t*>(&q1);
    dst[lane] = u0; dst[lane + 32] = u1;
}

__global__ void wprep_kernel(const float* __restrict__ w) {
    int i = blockIdx.x * blockDim.x + threadIdx.x;
    float4 v = reinterpret_cast<const float4*>(w)[i];
    __nv_bfloat162 p0 = __floats2bfloat162_rn(v.x, v.y), p1 = __floats2bfloat162_rn(v.z, v.w);
    uint2 u;
    u.x = *reinterpret_cast<uint32_t*>(&p0); u.y = *reinterpret_cast<uint32_t*>(&p1);
    reinterpret_cast<uint2*>(g_wbf)[i] = u;
}

__global__ void wsq_kernel(const float* __restrict__ w) {
    int u = blockIdx.x * blockDim.x + threadIdx.x;
    float s = 0.f;
#pragma unroll 8
    for (int f = 0; f < F_DIM; f++) {
        float v = w[(size_t)f * U_DIM + u];
        s = fmaf(v, v, s);
    }
    g_wsq[u] = s;
}

// ---------------------------------------------------------------- GEMM
__global__ __launch_bounds__(256, 2)
void rbf_gemm_kernel(float* __restrict__ out) {
    extern __shared__ char smem[];
    const uint32_t sb = smem_u32(smem);
    const int tid = threadIdx.x, lane = tid & 31, wi = tid >> 5;
    const int warp_m = wi & 3, warp_n = wi >> 2;

    const int u_tile = blockIdx.x & 7;          // u fastest -> L2 sharing of x stream
    const int slice = blockIdx.x >> 3;
    const int u0 = u_tile * TILE;
    const int b_begin = (slice * NB_TILES) / NSLICE;
    const int b_end = ((slice + 1) * NB_TILES) / NSLICE;
    const int C = (b_end - b_begin) * 4;        // 64-wide k-chunks total

    // ---- B (w tile, full K=256): 4096 16B vecs, swizzled ----
    for (int i = tid; i < 4096; i += 256) {
        int k = i >> 4, c = i & 15;
        uint32_t dst = sb + SM_B + (uint32_t)(k * 256 + ((c ^ (k & 7)) << 4));
        cp16(dst, (const char*)(g_wbf + (size_t)k * U_DIM + u0) + c * 16);
    }
    if (tid < 32) {
        float4 v = reinterpret_cast<const float4*>(g_wsq + u0)[tid];
        reinterpret_cast<float4*>(smem + SM_WSQ)[tid] = v;
    }
    CP_COMMIT();

    // ---- prologue: fill ring ----
    for (int c = 0; c < NS && c < C; c++) {
        size_t base = ((size_t)(b_begin + (c >> 2)) * TILE) * F_DIM + (size_t)(c & 3) * 64;
        uint32_t abuf = sb + SM_A + (uint32_t)((c % NS) * 16384);
        for (int i = tid; i < 1024; i += 256) {
            int r = i >> 3, cc = i & 7;
            cp16(abuf + (uint32_t)(r * 128 + ((cc ^ (r & 7)) << 4)),
                 g_xbf + base + (size_t)r * F_DIM + cc * 8);
        }
        CP_COMMIT();
    }

    float acc[2][8][4];
    const int lr = lane & 15, lc = lane >> 4;
    const int g = lane >> 2, cq = (lane & 3) * 2;
    const float* ws = reinterpret_cast<const float*>(smem + SM_WSQ);

    for (int c = 0; c < C; c++) {
        const int kc = c & 3;
        CP_WAIT(NS - 1);
        __syncthreads();

        if (kc == 0) {
#pragma unroll
            for (int mt = 0; mt < 2; mt++)
#pragma unroll
                for (int nt = 0; nt < 8; nt++)
#pragma unroll
                    for (int i = 0; i < 4; i++) acc[mt][nt][i] = 0.f;
        }

        const uint32_t abuf = sb + SM_A + (uint32_t)((c % NS) * 16384);
#pragma unroll
        for (int kk = 0; kk < 64; kk += 16) {
            uint32_t a_frag[2][4];
#pragma unroll
            for (int mt = 0; mt < 2; mt++) {
                int r = warp_m * 32 + mt * 16 + lr;
                int cch = (kk >> 3) + lc;
                uint32_t addr = abuf + (uint32_t)(r * 128 + ((cch ^ (r & 7)) << 4));
                ldm_x4(a_frag[mt][0], a_frag[mt][1], a_frag[mt][2], a_frag[mt][3], addr);
            }
            uint32_t b_frag[8][2];
#pragma unroll
            for (int np = 0; np < 4; np++) {
                int krow = kc * 64 + kk + lr;
                int cch = warp_n * 8 + np * 2 + lc;
                uint32_t addr = sb + SM_B + (uint32_t)(krow * 256 + ((cch ^ (krow & 7)) << 4));
                uint32_t r0, r1, r2, r3;
                ldm_x4_t(r0, r1, r2, r3, addr);
                b_frag[np * 2][0] = r0;     b_frag[np * 2][1] = r1;
                b_frag[np * 2 + 1][0] = r2; b_frag[np * 2 + 1][1] = r3;
            }
#pragma unroll
            for (int mt = 0; mt < 2; mt++)
#pragma unroll
                for (int nt = 0; nt < 8; nt++)
                    mma_16816(acc[mt][nt], a_frag[mt], b_frag[nt]);
        }
        __syncthreads();

        // refill this ring slot with chunk c+NS
        if (c + NS < C) {
            int cn = c + NS;
            size_t base = ((size_t)(b_begin + (cn >> 2)) * TILE) * F_DIM + (size_t)(cn & 3) * 64;
            for (int i = tid; i < 1024; i += 256) {
                int r = i >> 3, cc = i & 7;
                cp16(abuf + (uint32_t)(r * 128 + ((cc ^ (r & 7)) << 4)),
                     g_xbf + base + (size_t)r * F_DIM + cc * 8);
            }
        }
        CP_COMMIT();

        // epilogue overlaps in-flight cp.async (and the co-resident CTA's MMAs)
        if (kc == 3) {
            int bt = b_begin + (c >> 2);
#pragma unroll
            for (int mt = 0; mt < 2; mt++) {
                int rloc = warp_m * 32 + mt * 16 + g;
                float xlo = __ldg(&g_xsq[bt * TILE + rloc]);
                float xhi = __ldg(&g_xsq[bt * TILE + rloc + 8]);
                size_t row_lo = (size_t)(bt * TILE + rloc) * U_DIM;
                size_t row_hi = row_lo + (size_t)8 * U_DIM;
#pragma unroll
                for (int nt = 0; nt < 8; nt++) {
                    int cloc = warp_n * 64 + nt * 8 + cq;
                    float w0 = ws[cloc], w1 = ws[cloc + 1];
                    float2 vlo, vhi;
                    vlo.x = fmaf(-2.f, acc[mt][nt][0], xlo + w0);
                    vlo.y = fmaf(-2.f, acc[mt][nt][1], xlo + w1);
                    vhi.x = fmaf(-2.f, acc[mt][nt][2], xhi + w0);
                    vhi.y = fmaf(-2.f, acc[mt][nt][3], xhi + w1);
                    __stcs(reinterpret_cast<float2*>(out + row_lo + u0 + cloc), vlo);
                    __stcs(reinterpret_cast<float2*>(out + row_hi + u0 + cloc), vhi);
                }
            }
        }
    }
}

extern "C" void kernel_launch(void* const* d_in, const int* in_sizes, int n_in,
                              void* d_out, int out_size) {
    const float* x = (const float*)d_in[0];
    const float* w = (const float*)d_in[1];
    float* out = (float*)d_out;

    cudaFuncSetAttribute(rbf_gemm_kernel, cudaFuncAttributeMaxDynamicSharedMemorySize, SM_TOT);

    xprep_kernel<<<B_DIM / 8, 256>>>(x);
    wprep_kernel<<<(F_DIM * U_DIM / 4) / 256, 256>>>(w);
    wsq_kernel<<<U_DIM / 256, 256>>>(w);
    rbf_gemm_kernel<<<NU_TILES * NSLICE, 256, SM_TOT>>>(out);
}

// round 5
// speedup vs baseline: 2.8389x; 1.0527x over previous
#include <cuda_runtime.h>
#include <cuda_bf16.h>
#include <cstdint>

// out[b,u] = ||x_b||^2 - 2 * (x@w)[b,u] + ||w_u||^2
// x: [65536,256] f32, w: [256,1024] f32, out: [65536,1024] f32
//
// mma.sync.m16n8k16.bf16. Persistent CTAs, 2 CTAs/SM, 128 threads each.
// Warp tile 64x64 (2x2 warp grid over a 128x128 CTA tile) -> LDSM bytes per MMA
// cut 1.5x vs 32x64 (smem crossbar was the binding pipe at 64.6% vs tensor 44.4%).
// Single __syncthreads per k-chunk, 3-stage cp.async ring.

#define B_DIM 65536
#define F_DIM 256
#define U_DIM 1024
#define TILE  128
#define NB_TILES (B_DIM / TILE)   // 512
#define NU_TILES (U_DIM / TILE)   // 8
#define NSLICE   36               // 8 * 36 = 288 CTAs, 2 per SM on 144 SMs
#define NS       3                // cp.async ring stages (16KB each)

__device__ __nv_bfloat16 g_xbf[(size_t)B_DIM * F_DIM];  // 32 MB
__device__ __nv_bfloat16 g_wbf[(size_t)F_DIM * U_DIM];  // 512 KB
__device__ float g_xsq[B_DIM];
__device__ float g_wsq[U_DIM];

// smem: B tile 64KB | A ring 3x16KB | wsq 512B => 115200 B/CTA (2 per SM)
#define SM_B    0
#define SM_A    65536
#define SM_WSQ  (65536 + NS * 16384)
#define SM_TOT  (SM_WSQ + 512)

// ---------------------------------------------------------------- helpers
__device__ __forceinline__ uint32_t smem_u32(const void* p) {
    uint32_t a;
    asm("{ .reg .u64 t; cvta.to.shared.u64 t, %1; cvt.u32.u64 %0, t; }" : "=r"(a) : "l"(p));
    return a;
}
__device__ __forceinline__ void cp16(uint32_t dst, const void* src) {
    asm volatile("cp.async.cg.shared.global [%0], [%1], 16;"
                 :: "r"(dst), "l"(__cvta_generic_to_global(src)) : "memory");
}
#define CP_COMMIT() asm volatile("cp.async.commit_group;" ::: "memory")
#define CP_WAIT(N)  asm volatile("cp.async.wait_group %0;" :: "n"(N) : "memory")

__device__ __forceinline__ void ldm_x4(uint32_t& r0, uint32_t& r1, uint32_t& r2, uint32_t& r3,
                                       uint32_t addr) {
    asm volatile("ldmatrix.sync.aligned.m8n8.x4.shared.b16 {%0,%1,%2,%3}, [%4];"
                 : "=r"(r0), "=r"(r1), "=r"(r2), "=r"(r3) : "r"(addr));
}
__device__ __forceinline__ void ldm_x4_t(uint32_t& r0, uint32_t& r1, uint32_t& r2, uint32_t& r3,
                                         uint32_t addr) {
    asm volatile("ldmatrix.sync.aligned.m8n8.x4.trans.shared.b16 {%0,%1,%2,%3}, [%4];"
                 : "=r"(r0), "=r"(r1), "=r"(r2), "=r"(r3) : "r"(addr));
}
__device__ __forceinline__ void mma_16816(float* c, const uint32_t* a, const uint32_t* b) {
    asm volatile("mma.sync.aligned.m16n8k16.row.col.f32.bf16.bf16.f32 "
                 "{%0,%1,%2,%3}, {%4,%5,%6,%7}, {%8,%9}, {%0,%1,%2,%3};"
                 : "+f"(c[0]), "+f"(c[1]), "+f"(c[2]), "+f"(c[3])
                 : "r"(a[0]), "r"(a[1]), "r"(a[2]), "r"(a[3]), "r"(b[0]), "r"(b[1]));
}

// ---------------------------------------------------------------- prep kernels
__global__ void xprep_kernel(const float* __restrict__ x) {
    int row = blockIdx.x * 8 + (threadIdx.x >> 5);
    int lane = threadIdx.x & 31;
    const float4* src = reinterpret_cast<const float4*>(x + (size_t)row * F_DIM);
    float4 a = src[lane], b = src[lane + 32];
    float s = a.x * a.x + a.y * a.y + a.z * a.z + a.w * a.w
            + b.x * b.x + b.y * b.y + b.z * b.z + b.w * b.w;
#pragma unroll
    for (int o = 16; o > 0; o >>= 1) s += __shfl_down_sync(0xffffffffu, s, o);
    if (lane == 0) g_xsq[row] = s;
    uint2* dst = reinterpret_cast<uint2*>(g_xbf + (size_t)row * F_DIM);
    __nv_bfloat162 p0 = __floats2bfloat162_rn(a.x, a.y), p1 = __floats2bfloat162_rn(a.z, a.w);
    __nv_bfloat162 q0 = __floats2bfloat162_rn(b.x, b.y), q1 = __floats2bfloat162_rn(b.z, b.w);
    uint2 u0, u1;
    u0.x = *reinterpret_cast<uint32_t*>(&p0); u0.y = *reinterpret_cast<uint32_t*>(&p1);
    u1.x = *reinterpret_cast<uint32_t*>(&q0); u1.y = *reinterpret_cast<uint32_t*>(&q1);
    dst[lane] = u0; dst[lane + 32] = u1;
}

__global__ void wprep_kernel(const float* __restrict__ w) {
    int i = blockIdx.x * blockDim.x + threadIdx.x;
    float4 v = reinterpret_cast<const float4*>(w)[i];
    __nv_bfloat162 p0 = __floats2bfloat162_rn(v.x, v.y), p1 = __floats2bfloat162_rn(v.z, v.w);
    uint2 u;
    u.x = *reinterpret_cast<uint32_t*>(&p0); u.y = *reinterpret_cast<uint32_t*>(&p1);
    reinterpret_cast<uint2*>(g_wbf)[i] = u;
}

__global__ void wsq_kernel(const float* __restrict__ w) {
    int u = blockIdx.x * blockDim.x + threadIdx.x;
    float s = 0.f;
#pragma unroll 8
    for (int f = 0; f < F_DIM; f++) {
        float v = w[(size_t)f * U_DIM + u];
        s = fmaf(v, v, s);
    }
    g_wsq[u] = s;
}

// ---------------------------------------------------------------- GEMM
__global__ __launch_bounds__(128)
void rbf_gemm_kernel(float* __restrict__ out) {
    extern __shared__ char smem[];
    const uint32_t sb = smem_u32(smem);
    const int tid = threadIdx.x, lane = tid & 31, wi = tid >> 5;  // 4 warps
    const int warp_m = wi & 1, warp_n = wi >> 1;                  // 2x2, tiles 64x64

    const int u_tile = blockIdx.x & 7;          // u fastest -> L2 sharing of x stream
    const int slice = blockIdx.x >> 3;
    const int u0 = u_tile * TILE;
    const int b_begin = (slice * NB_TILES) / NSLICE;
    const int b_end = ((slice + 1) * NB_TILES) / NSLICE;
    const int C = (b_end - b_begin) * 4;        // 64-wide k-chunks

    // ---- B (w tile, full K=256): 4096 16B vecs, swizzled ----
    for (int i = tid; i < 4096; i += 128) {
        int k = i >> 4, c = i & 15;
        uint32_t dst = sb + SM_B + (uint32_t)(k * 256 + ((c ^ (k & 7)) << 4));
        cp16(dst, (const char*)(g_wbf + (size_t)k * U_DIM + u0) + c * 16);
    }
    if (tid < 32) {
        float4 v = reinterpret_cast<const float4*>(g_wsq + u0)[tid];
        reinterpret_cast<float4*>(smem + SM_WSQ)[tid] = v;
    }
    CP_COMMIT();

    // ---- prologue: chunks 0..NS-2 ----
    for (int c = 0; c < NS - 1 && c < C; c++) {
        size_t base = ((size_t)(b_begin + (c >> 2)) * TILE) * F_DIM + (size_t)(c & 3) * 64;
        uint32_t abuf = sb + SM_A + (uint32_t)((c % NS) * 16384);
        for (int i = tid; i < 1024; i += 128) {
            int r = i >> 3, cc = i & 7;
            cp16(abuf + (uint32_t)(r * 128 + ((cc ^ (r & 7)) << 4)),
                 g_xbf + base + (size_t)r * F_DIM + cc * 8);
        }
        CP_COMMIT();
    }

    float acc[4][8][4];
    const int lr = lane & 15, lc = lane >> 4;
    const int g = lane >> 2, cq = (lane & 3) * 2;
    const float* ws = reinterpret_cast<const float*>(smem + SM_WSQ);

    for (int c = 0; c < C; c++) {
        const int kc = c & 3;
        CP_WAIT(NS - 2);          // chunk c resident
        __syncthreads();          // all warps done with chunk c-1's slot

        // prefetch chunk c+NS-1 into the slot consumed at c-1 (safe after sync)
        {
            int cn = c + NS - 1;
            if (cn < C) {
                size_t base = ((size_t)(b_begin + (cn >> 2)) * TILE) * F_DIM + (size_t)(cn & 3) * 64;
                uint32_t abuf = sb + SM_A + (uint32_t)((cn % NS) * 16384);
                for (int i = tid; i < 1024; i += 128) {
                    int r = i >> 3, cc = i & 7;
                    cp16(abuf + (uint32_t)(r * 128 + ((cc ^ (r & 7)) << 4)),
                         g_xbf + base + (size_t)r * F_DIM + cc * 8);
                }
            }
            CP_COMMIT();
        }

        if (kc == 0) {
#pragma unroll
            for (int mt = 0; mt < 4; mt++)
#pragma unroll
                for (int nt = 0; nt < 8; nt++)
#pragma unroll
                    for (int i = 0; i < 4; i++) acc[mt][nt][i] = 0.f;
        }

        // ---- compute chunk c: 64 k, 4 k-steps, warp tile 64x64 ----
        const uint32_t abuf = sb + SM_A + (uint32_t)((c % NS) * 16384);
#pragma unroll
        for (int kk = 0; kk < 64; kk += 16) {
            uint32_t a_frag[4][4];
#pragma unroll
            for (int mt = 0; mt < 4; mt++) {
                int r = warp_m * 64 + mt * 16 + lr;
                int cch = (kk >> 3) + lc;
                uint32_t addr = abuf + (uint32_t)(r * 128 + ((cch ^ (r & 7)) << 4));
                ldm_x4(a_frag[mt][0], a_frag[mt][1], a_frag[mt][2], a_frag[mt][3], addr);
            }
            uint32_t b_frag[8][2];
#pragma unroll
            for (int np = 0; np < 4; np++) {
                int krow = kc * 64 + kk + lr;
                int cch = warp_n * 8 + np * 2 + lc;
                uint32_t addr = sb + SM_B + (uint32_t)(krow * 256 + ((cch ^ (krow & 7)) << 4));
                uint32_t r0, r1, r2, r3;
                ldm_x4_t(r0, r1, r2, r3, addr);
                b_frag[np * 2][0] = r0;     b_frag[np * 2][1] = r1;
                b_frag[np * 2 + 1][0] = r2; b_frag[np * 2 + 1][1] = r3;
            }
#pragma unroll
            for (int mt = 0; mt < 4; mt++)
#pragma unroll
                for (int nt = 0; nt < 8; nt++)
                    mma_16816(acc[mt][nt], a_frag[mt], b_frag[nt]);
        }

        // ---- epilogue ----
        if (kc == 3) {
            int bt = b_begin + (c >> 2);
#pragma unroll
            for (int mt = 0; mt < 4; mt++) {
                int rloc = warp_m * 64 + mt * 16 + g;
                float xlo = __ldg(&g_xsq[bt * TILE + rloc]);
                float xhi = __ldg(&g_xsq[bt * TILE + rloc + 8]);
                size_t row_lo = (size_t)(bt * TILE + rloc) * U_DIM;
                size_t row_hi = row_lo + (size_t)8 * U_DIM;
#pragma unroll
                for (int nt = 0; nt < 8; nt++) {
                    int cloc = warp_n * 64 + nt * 8 + cq;
                    float w0 = ws[cloc], w1 = ws[cloc + 1];
                    float2 vlo, vhi;
                    vlo.x = fmaf(-2.f, acc[mt][nt][0], xlo + w0);
                    vlo.y = fmaf(-2.f, acc[mt][nt][1], xlo + w1);
                    vhi.x = fmaf(-2.f, acc[mt][nt][2], xhi + w0);
                    vhi.y = fmaf(-2.f, acc[mt][nt][3], xhi + w1);
                    __stcs(reinterpret_cast<float2*>(out + row_lo + u0 + cloc), vlo);
                    __stcs(reinterpret_cast<float2*>(out + row_hi + u0 + cloc), vhi);
                }
            }
        }
    }
}

extern "C" void kernel_launch(void* const* d_in, const int* in_sizes, int n_in,
                              void* d_out, int out_size) {
    const float* x = (const float*)d_in[0];
    const float* w = (const float*)d_in[1];
    float* out = (float*)d_out;

    cudaFuncSetAttribute(rbf_gemm_kernel, cudaFuncAttributeMaxDynamicSharedMemorySize, SM_TOT);

    xprep_kernel<<<B_DIM / 8, 256>>>(x);
    wprep_kernel<<<(F_DIM * U_DIM / 4) / 256, 256>>>(w);
    wsq_kernel<<<U_DIM / 256, 256>>>(w);
    rbf_gemm_kernel<<<NU_TILES * NSLICE, 128, SM_TOT>>>(out);
}

// round 7
// speedup vs baseline: 2.9837x; 1.0510x over previous
#include <cuda_runtime.h>
#include <cuda_bf16.h>
#include <cstdint>

// out[b,u] = ||x_b||^2 - 2 * (x@w)[b,u] + ||w_u||^2
// x: [65536,256] f32, w: [256,1024] f32, out: [65536,1024] f32
//
// mma.sync.m16n8k16.bf16. Persistent CTAs, 3 CTAs/SM, 128 threads each,
// warp tile 64x64. BOTH A (x) and B (w) k-chunks streamed through a 2-stage
// cp.async double buffer (smem 64.5KB/CTA -> 3 CTAs/SM). One sync per chunk.

#define B_DIM 65536
#define F_DIM 256
#define U_DIM 1024
#define TILE  128
#define NB_TILES (B_DIM / TILE)   // 512
#define NU_TILES (U_DIM / TILE)   // 8
#define NSLICE   54               // 8 * 54 = 432 CTAs = 3/SM on 144 SMs
#define NS       2                // double buffer

__device__ __nv_bfloat16 g_xbf[(size_t)B_DIM * F_DIM];  // 32 MB
__device__ __nv_bfloat16 g_wbf[(size_t)F_DIM * U_DIM];  // 512 KB (L2-resident)
__device__ float g_xsq[B_DIM];
__device__ float g_wsq[U_DIM];

// smem: A ring 2x16KB | B ring 2x16KB | wsq 512B => 66048 B/CTA
#define SM_A    0
#define SM_B    (NS * 16384)
#define SM_WSQ  (2 * NS * 16384)
#define SM_TOT  (SM_WSQ + 512)

// ---------------------------------------------------------------- helpers
__device__ __forceinline__ uint32_t smem_u32(const void* p) {
    uint32_t a;
    asm("{ .reg .u64 t; cvta.to.shared.u64 t, %1; cvt.u32.u64 %0, t; }" : "=r"(a) : "l"(p));
    return a;
}
__device__ __forceinline__ void cp16(uint32_t dst, const void* src) {
    asm volatile("cp.async.cg.shared.global [%0], [%1], 16;"
                 :: "r"(dst), "l"(__cvta_generic_to_global(src)) : "memory");
}
#define CP_COMMIT() asm volatile("cp.async.commit_group;" ::: "memory")
#define CP_WAIT(N)  asm volatile("cp.async.wait_group %0;" :: "n"(N) : "memory")

__device__ __forceinline__ void ldm_x4(uint32_t& r0, uint32_t& r1, uint32_t& r2, uint32_t& r3,
                                       uint32_t addr) {
    asm volatile("ldmatrix.sync.aligned.m8n8.x4.shared.b16 {%0,%1,%2,%3}, [%4];"
                 : "=r"(r0), "=r"(r1), "=r"(r2), "=r"(r3) : "r"(addr));
}
__device__ __forceinline__ void ldm_x4_t(uint32_t& r0, uint32_t& r1, uint32_t& r2, uint32_t& r3,
                                         uint32_t addr) {
    asm volatile("ldmatrix.sync.aligned.m8n8.x4.trans.shared.b16 {%0,%1,%2,%3}, [%4];"
                 : "=r"(r0), "=r"(r1), "=r"(r2), "=r"(r3) : "r"(addr));
}
__device__ __forceinline__ void mma_16816(float* c, const uint32_t* a, const uint32_t* b) {
    asm volatile("mma.sync.aligned.m16n8k16.row.col.f32.bf16.bf16.f32 "
                 "{%0,%1,%2,%3}, {%4,%5,%6,%7}, {%8,%9}, {%0,%1,%2,%3};"
                 : "+f"(c[0]), "+f"(c[1]), "+f"(c[2]), "+f"(c[3])
                 : "r"(a[0]), "r"(a[1]), "r"(a[2]), "r"(a[3]), "r"(b[0]), "r"(b[1]));
}

// ---------------------------------------------------------------- fused prep
// blocks [0, 8192): x -> bf16 + row sumsq (8 rows per block)
// blocks [8192, 8448): w -> bf16 (1024 float4 per block)
// blocks [8448, 8452): wsq (256 u per block)
#define XPREP_BLOCKS 8192
#define WPREP_BLOCKS 256
__global__ __launch_bounds__(256) void prep_kernel(const float* __restrict__ x,
                                                   const float* __restrict__ w) {
    int blk = blockIdx.x;
    if (blk < XPREP_BLOCKS) {
        int row = blk * 8 + (threadIdx.x >> 5);
        int lane = threadIdx.x & 31;
        const float4* src = reinterpret_cast<const float4*>(x + (size_t)row * F_DIM);
        float4 a = src[lane], b = src[lane + 32];
        float s = a.x * a.x + a.y * a.y + a.z * a.z + a.w * a.w
                + b.x * b.x + b.y * b.y + b.z * b.z + b.w * b.w;
#pragma unroll
        for (int o = 16; o > 0; o >>= 1) s += __shfl_down_sync(0xffffffffu, s, o);
        if (lane == 0) g_xsq[row] = s;
        uint2* dst = reinterpret_cast<uint2*>(g_xbf + (size_t)row * F_DIM);
        __nv_bfloat162 p0 = __floats2bfloat162_rn(a.x, a.y), p1 = __floats2bfloat162_rn(a.z, a.w);
        __nv_bfloat162 q0 = __floats2bfloat162_rn(b.x, b.y), q1 = __floats2bfloat162_rn(b.z, b.w);
        uint2 u0, u1;
        u0.x = *reinterpret_cast<uint32_t*>(&p0); u0.y = *reinterpret_cast<uint32_t*>(&p1);
        u1.x = *reinterpret_cast<uint32_t*>(&q0); u1.y = *reinterpret_cast<uint32_t*>(&q1);
        dst[lane] = u0; dst[lane + 32] = u1;
    } else if (blk < XPREP_BLOCKS + WPREP_BLOCKS) {
        int i = (blk - XPREP_BLOCKS) * 256 + threadIdx.x;
        float4 v = reinterpret_cast<const float4*>(w)[i];
        __nv_bfloat162 p0 = __floats2bfloat162_rn(v.x, v.y), p1 = __floats2bfloat162_rn(v.z, v.w);
        uint2 u;
        u.x = *reinterpret_cast<uint32_t*>(&p0); u.y = *reinterpret_cast<uint32_t*>(&p1);
        reinterpret_cast<uint2*>(g_wbf)[i] = u;
    } else {
        int u = (blk - XPREP_BLOCKS - WPREP_BLOCKS) * 256 + threadIdx.x;
        float s = 0.f;
#pragma unroll 8
        for (int f = 0; f < F_DIM; f++) {
            float v = w[(size_t)f * U_DIM + u];
            s = fmaf(v, v, s);
        }
        g_wsq[u] = s;
    }
}

// ---------------------------------------------------------------- GEMM
__global__ __launch_bounds__(128, 3)
void rbf_gemm_kernel(float* __restrict__ out) {
    extern __shared__ char smem[];
    const uint32_t sb = smem_u32(smem);
    const int tid = threadIdx.x, lane = tid & 31, wi = tid >> 5;  // 4 warps
    const int warp_m = wi & 1, warp_n = wi >> 1;                  // 2x2, tiles 64x64

    const int u_tile = blockIdx.x & 7;          // u fastest -> L2 sharing of x stream
    const int slice = blockIdx.x >> 3;
    const int u0 = u_tile * TILE;
    const int b_begin = (slice * NB_TILES) / NSLICE;
    const int b_end = ((slice + 1) * NB_TILES) / NSLICE;
    const int C = (b_end - b_begin) * 4;        // 64-wide k-chunks

    if (tid < 32) {
        float4 v = reinterpret_cast<const float4*>(g_wsq + u0)[tid];
        reinterpret_cast<float4*>(smem + SM_WSQ)[tid] = v;
    }

    // chunk loader: A = x[bt*128 .. +128, kc*64 .. +64], B = w[kc*64 .. +64, u0 .. +128]
    auto load_chunk = [&](int c) {
        int slot = c & 1, kc = c & 3, bt = b_begin + (c >> 2);
        uint32_t abuf = sb + SM_A + (uint32_t)(slot * 16384);
        size_t abase = ((size_t)bt * TILE) * F_DIM + (size_t)kc * 64;
        for (int i = tid; i < 1024; i += 128) {
            int r = i >> 3, cc = i & 7;   // 128 rows x 8 vecs (128B/row)
            cp16(abuf + (uint32_t)(r * 128 + ((cc ^ (r & 7)) << 4)),
                 g_xbf + abase + (size_t)r * F_DIM + cc * 8);
        }
        uint32_t bbuf = sb + SM_B + (uint32_t)(slot * 16384);
        const char* bbase = (const char*)(g_wbf + (size_t)kc * 64 * U_DIM + u0);
        for (int i = tid; i < 1024; i += 128) {
            int k = i >> 4, cc = i & 15;  // 64 k-rows x 16 vecs (256B/row)
            cp16(bbuf + (uint32_t)(k * 256 + ((cc ^ (k & 7)) << 4)),
                 bbase + (size_t)k * U_DIM * 2 + cc * 16);
        }
        CP_COMMIT();
    };

    load_chunk(0);

    float acc[4][8][4];
    const int lr = lane & 15, lc = lane >> 4;
    const int g = lane >> 2, cq = (lane & 3) * 2;
    const float* ws = reinterpret_cast<const float*>(smem + SM_WSQ);

    for (int c = 0; c < C; c++) {
        const int kc = c & 3, slot = c & 1;
        CP_WAIT(0);               // chunk c fully resident (this thread's copies)
        __syncthreads();          // cross-thread visibility + c-1 slot free

        if (c + 1 < C) load_chunk(c + 1);   // into the slot consumed at c-1

        if (kc == 0) {
#pragma unroll
            for (int mt = 0; mt < 4; mt++)
#pragma unroll
                for (int nt = 0; nt < 8; nt++)
#pragma unroll
                    for (int i = 0; i < 4; i++) acc[mt][nt][i] = 0.f;
        }

        // ---- compute chunk c: 64 k, 4 k-steps, warp tile 64x64 ----
        const uint32_t abuf = sb + SM_A + (uint32_t)(slot * 16384);
        const uint32_t bbuf = sb + SM_B + (uint32_t)(slot * 16384);
#pragma unroll
        for (int kk = 0; kk < 64; kk += 16) {
            uint32_t a_frag[4][4];
#pragma unroll
            for (int mt = 0; mt < 4; mt++) {
                int r = warp_m * 64 + mt * 16 + lr;
                int cch = (kk >> 3) + lc;
                uint32_t addr = abuf + (uint32_t)(r * 128 + ((cch ^ (r & 7)) << 4));
                ldm_x4(a_frag[mt][0], a_frag[mt][1], a_frag[mt][2], a_frag[mt][3], addr);
            }
            uint32_t b_frag[8][2];
#pragma unroll
            for (int np = 0; np < 4; np++) {
                int krow = kk + lr;   // within-chunk k row (0..63)
                int cch = warp_n * 8 + np * 2 + lc;
                uint32_t addr = bbuf + (uint32_t)(krow * 256 + ((cch ^ (krow & 7)) << 4));
                uint32_t r0, r1, r2, r3;
                ldm_x4_t(r0, r1, r2, r3, addr);
                b_frag[np * 2][0] = r0;     b_frag[np * 2][1] = r1;
                b_frag[np * 2 + 1][0] = r2; b_frag[np * 2 + 1][1] = r3;
            }
#pragma unroll
            for (int mt = 0; mt < 4; mt++)
#pragma unroll
                for (int nt = 0; nt < 8; nt++)
                    mma_16816(acc[mt][nt], a_frag[mt], b_frag[nt]);
        }

        // ---- epilogue ----
        if (kc == 3) {
            int bt = b_begin + (c >> 2);
#pragma unroll
            for (int mt = 0; mt < 4; mt++) {
                int rloc = warp_m * 64 + mt * 16 + g;
                float xlo = __ldg(&g_xsq[bt * TILE + rloc]);
                float xhi = __ldg(&g_xsq[bt * TILE + rloc + 8]);
                size_t row_lo = (size_t)(bt * TILE + rloc) * U_DIM;
                size_t row_hi = row_lo + (size_t)8 * U_DIM;
#pragma unroll
                for (int nt = 0; nt < 8; nt++) {
                    int cloc = warp_n * 64 + nt * 8 + cq;
                    float w0 = ws[cloc], w1 = ws[cloc + 1];
                    float2 vlo, vhi;
                    vlo.x = fmaf(-2.f, acc[mt][nt][0], xlo + w0);
                    vlo.y = fmaf(-2.f, acc[mt][nt][1], xlo + w1);
                    vhi.x = fmaf(-2.f, acc[mt][nt][2], xhi + w0);
                    vhi.y = fmaf(-2.f, acc[mt][nt][3], xhi + w1);
                    __stcs(reinterpret_cast<float2*>(out + row_lo + u0 + cloc), vlo);
                    __stcs(reinterpret_cast<float2*>(out + row_hi + u0 + cloc), vhi);
                }
            }
        }
    }
}

extern "C" void kernel_launch(void* const* d_in, const int* in_sizes, int n_in,
                              void* d_out, int out_size) {
    const float* x = (const float*)d_in[0];
    const float* w = (const float*)d_in[1];
    float* out = (float*)d_out;

    cudaFuncSetAttribute(rbf_gemm_kernel, cudaFuncAttributeMaxDynamicSharedMemorySize, SM_TOT);

    prep_kernel<<<XPREP_BLOCKS + WPREP_BLOCKS + U_DIM / 256, 256>>>(x, w);
    rbf_gemm_kernel<<<NU_TILES * NSLICE, 128, SM_TOT>>>(out);
}